// round 2
// baseline (speedup 1.0000x reference)
#include <cuda_runtime.h>
#include <cstdint>

#define DEV_INLINE __device__ __forceinline__

constexpr int B_  = 2;
constexpr int S_  = 2048;
constexpr int DM  = 2048;   // d_model
constexpr int NH  = 32;     // heads
constexpr int NKV = 8;      // kv heads
constexpr int DH  = 64;     // head dim
constexpr int KVW = NKV * DH;  // 512
constexpr float LOG2E = 1.4426950408889634f;

// Scratch (device globals — no runtime allocation allowed)
__device__ float g_q[(size_t)B_ * S_ * NH * DH];      // [B*S, 2048]
__device__ float g_k[(size_t)B_ * S_ * NKV * DH];     // [B*S, 512]
__device__ float g_v[(size_t)B_ * S_ * NKV * DH];     // [B*S, 512]
__device__ float g_attn[(size_t)B_ * S_ * NH * DH];   // [B*S, 2048]

DEV_INLINE uint32_t f2tf32(float x) {
    uint32_t u;
    asm("cvt.rna.tf32.f32 %0, %1;" : "=r"(u) : "f"(x));
    return u;
}

DEV_INLINE void mma8(float* d, const uint32_t* a, const uint32_t* b, const float* c) {
    asm volatile(
        "mma.sync.aligned.m16n8k8.row.col.f32.tf32.tf32.f32 "
        "{%0,%1,%2,%3}, {%4,%5,%6,%7}, {%8,%9}, {%10,%11,%12,%13};\n"
        : "=f"(d[0]), "=f"(d[1]), "=f"(d[2]), "=f"(d[3])
        : "r"(a[0]), "r"(a[1]), "r"(a[2]), "r"(a[3]),
          "r"(b[0]), "r"(b[1]),
          "f"(c[0]), "f"(c[1]), "f"(c[2]), "f"(c[3]));
}

// ---------------------------------------------------------------------------
// Generic tf32 GEMM.
//   TRANS_B = true :  C[M,N] = A[M,K] * B[N,K]^T   (A,B row-major, K contiguous)
//   TRANS_B = false:  C[M,N] = A[M,K] * B[K,N]     (B row-major, N contiguous)
// Block tile 128x128x32, 256 threads (8 warps, 2x4), warp tile 64x32.
// ---------------------------------------------------------------------------
template <bool TRANS_B>
__global__ void __launch_bounds__(256)
gemm_tf32(const float* __restrict__ A, const float* __restrict__ Bm,
          float* __restrict__ C, int M, int N, int K)
{
    constexpr int BM = 128, BN = 128, BK = 32;
    constexpr int LDA   = BK + 4;   // 36
    constexpr int LDB_T = BK + 4;   // [n][k]
    constexpr int LDB_N = BN + 4;   // [k][n] 132

    __shared__ uint32_t As[BM * LDA];
    __shared__ uint32_t Bs[TRANS_B ? (BN * LDB_T) : (BK * LDB_N)];

    const int tid  = threadIdx.x;
    const int warp = tid >> 5, lane = tid & 31;
    const int gID  = lane >> 2, tig = lane & 3;
    const int wm   = warp >> 2, wn = warp & 3;
    const int bm   = blockIdx.y * BM, bn = blockIdx.x * BN;

    float acc[4][4][4];
#pragma unroll
    for (int i = 0; i < 4; i++)
#pragma unroll
        for (int j = 0; j < 4; j++)
#pragma unroll
            for (int l = 0; l < 4; l++) acc[i][j][l] = 0.f;

    const int KT = K / BK;
    for (int kt = 0; kt < KT; ++kt) {
        const int k0 = kt * BK;
        __syncthreads();
        // A tile: 128 x 32
#pragma unroll
        for (int p = 0; p < 4; p++) {
            int r = p * 32 + (tid >> 3), c4 = (tid & 7) << 2;
            float4 v = *reinterpret_cast<const float4*>(A + (size_t)(bm + r) * K + k0 + c4);
            uint32_t* d = &As[r * LDA + c4];
            d[0] = f2tf32(v.x); d[1] = f2tf32(v.y); d[2] = f2tf32(v.z); d[3] = f2tf32(v.w);
        }
        if constexpr (TRANS_B) {
            // B tile: 128(n) x 32(k), K contiguous
#pragma unroll
            for (int p = 0; p < 4; p++) {
                int r = p * 32 + (tid >> 3), c4 = (tid & 7) << 2;
                float4 v = *reinterpret_cast<const float4*>(Bm + (size_t)(bn + r) * K + k0 + c4);
                uint32_t* d = &Bs[r * LDB_T + c4];
                d[0] = f2tf32(v.x); d[1] = f2tf32(v.y); d[2] = f2tf32(v.z); d[3] = f2tf32(v.w);
            }
        } else {
            // B tile: 32(k) x 128(n), N contiguous
#pragma unroll
            for (int p = 0; p < 4; p++) {
                int r = p * 8 + (tid >> 5), c4 = (tid & 31) << 2;
                float4 v = *reinterpret_cast<const float4*>(Bm + (size_t)(k0 + r) * N + bn + c4);
                uint32_t* d = &Bs[r * LDB_N + c4];
                d[0] = f2tf32(v.x); d[1] = f2tf32(v.y); d[2] = f2tf32(v.z); d[3] = f2tf32(v.w);
            }
        }
        __syncthreads();

#pragma unroll
        for (int ks = 0; ks < 4; ks++) {
            uint32_t af[4][4], bf[4][2];
#pragma unroll
            for (int mt = 0; mt < 4; mt++) {
                int r = wm * 64 + mt * 16;
                int c = ks * 8;
                af[mt][0] = As[(r + gID) * LDA + c + tig];
                af[mt][1] = As[(r + gID + 8) * LDA + c + tig];
                af[mt][2] = As[(r + gID) * LDA + c + tig + 4];
                af[mt][3] = As[(r + gID + 8) * LDA + c + tig + 4];
            }
#pragma unroll
            for (int nt = 0; nt < 4; nt++) {
                int n = wn * 32 + nt * 8 + gID;
                int kk = ks * 8 + tig;
                if constexpr (TRANS_B) {
                    bf[nt][0] = Bs[n * LDB_T + kk];
                    bf[nt][1] = Bs[n * LDB_T + kk + 4];
                } else {
                    bf[nt][0] = Bs[kk * LDB_N + n];
                    bf[nt][1] = Bs[(kk + 4) * LDB_N + n];
                }
            }
#pragma unroll
            for (int mt = 0; mt < 4; mt++)
#pragma unroll
                for (int nt = 0; nt < 4; nt++)
                    mma8(acc[mt][nt], af[mt], bf[nt], acc[mt][nt]);
        }
    }

    // Epilogue
#pragma unroll
    for (int mt = 0; mt < 4; mt++) {
        int r0 = bm + wm * 64 + mt * 16 + gID;
#pragma unroll
        for (int nt = 0; nt < 4; nt++) {
            int cc = bn + wn * 32 + nt * 8 + 2 * tig;
            *reinterpret_cast<float2*>(C + (size_t)r0 * N + cc) =
                make_float2(acc[mt][nt][0], acc[mt][nt][1]);
            *reinterpret_cast<float2*>(C + (size_t)(r0 + 8) * N + cc) =
                make_float2(acc[mt][nt][2], acc[mt][nt][3]);
        }
    }
}

// ---------------------------------------------------------------------------
// Flash attention (causal, GQA). Block = one (b, head, 64-row q tile).
// 128 threads (4 warps), each warp owns 16 q rows. Q kept in registers as
// A-fragments; one shared K/V buffer reused sequentially (smem < 48KB).
// ---------------------------------------------------------------------------
__global__ void __launch_bounds__(128)
flash_kernel(const float* __restrict__ gq, const float* __restrict__ gk,
             const float* __restrict__ gv, float* __restrict__ go)
{
    constexpr int LD = DH + 4;  // 68
    __shared__ uint32_t QP[64 * LD];  // Q tile first, reused for P after
    __shared__ uint32_t KV[64 * LD];  // K tile, then V tile

    const int qi = blockIdx.x, h = blockIdx.y, b = blockIdx.z;
    const int kvh = h >> 2;  // rep = NH/NKV = 4
    const int tid = threadIdx.x, warp = tid >> 5, lane = tid & 31;
    const int gID = lane >> 2, tig = lane & 3;

    // Load Q tile (tf32)
    {
        const float* qb = gq + (size_t)(b * S_ + qi * 64) * DM + h * DH;
#pragma unroll
        for (int p = 0; p < 8; p++) {
            int r = p * 8 + (tid >> 4), c4 = (tid & 15) << 2;
            float4 v = *reinterpret_cast<const float4*>(qb + (size_t)r * DM + c4);
            uint32_t* d = &QP[r * LD + c4];
            d[0] = f2tf32(v.x); d[1] = f2tf32(v.y); d[2] = f2tf32(v.z); d[3] = f2tf32(v.w);
        }
    }
    __syncthreads();

    // Pull Q into register A-fragments (16 rows x 64 cols per warp)
    uint32_t qf[8][4];
    {
        int r0 = warp * 16;
#pragma unroll
        for (int ks = 0; ks < 8; ks++) {
            int c = ks * 8;
            qf[ks][0] = QP[(r0 + gID) * LD + c + tig];
            qf[ks][1] = QP[(r0 + gID + 8) * LD + c + tig];
            qf[ks][2] = QP[(r0 + gID) * LD + c + tig + 4];
            qf[ks][3] = QP[(r0 + gID + 8) * LD + c + tig + 4];
        }
    }

    float m0 = -1e30f, m1 = -1e30f, l0 = 0.f, l1 = 0.f;
    float o[8][4];
#pragma unroll
    for (int nt = 0; nt < 8; nt++)
#pragma unroll
        for (int i = 0; i < 4; i++) o[nt][i] = 0.f;

    const float* kb0 = gk + (size_t)(b * S_) * KVW + kvh * DH;
    const float* vb0 = gv + (size_t)(b * S_) * KVW + kvh * DH;

    for (int j = 0; j <= qi; j++) {
        __syncthreads();  // KV free (previous PV reads complete), P region free
        // Load K tile
        {
            const float* kb = kb0 + (size_t)j * 64 * KVW;
#pragma unroll
            for (int p = 0; p < 8; p++) {
                int r = p * 8 + (tid >> 4), c4 = (tid & 15) << 2;
                float4 v = *reinterpret_cast<const float4*>(kb + (size_t)r * KVW + c4);
                uint32_t* d = &KV[r * LD + c4];
                d[0] = f2tf32(v.x); d[1] = f2tf32(v.y); d[2] = f2tf32(v.z); d[3] = f2tf32(v.w);
            }
        }
        __syncthreads();

        // S = Q * K^T (16 rows x 64 key cols per warp)
        float s[8][4];
#pragma unroll
        for (int nt = 0; nt < 8; nt++)
#pragma unroll
            for (int i = 0; i < 4; i++) s[nt][i] = 0.f;
#pragma unroll
        for (int ks = 0; ks < 8; ks++) {
#pragma unroll
            for (int nt = 0; nt < 8; nt++) {
                uint32_t bf[2];
                bf[0] = KV[(nt * 8 + gID) * LD + ks * 8 + tig];
                bf[1] = KV[(nt * 8 + gID) * LD + ks * 8 + tig + 4];
                mma8(s[nt], qf[ks], bf, s[nt]);
            }
        }

        // Scale + causal mask + online softmax
        const bool diag = (j == qi);
        float mx0 = -1e30f, mx1 = -1e30f;
#pragma unroll
        for (int nt = 0; nt < 8; nt++) {
#pragma unroll
            for (int i = 0; i < 4; i++) {
                float sv = s[nt][i] * 0.125f;  // 1/sqrt(64)
                if (diag) {
                    int col = nt * 8 + 2 * tig + (i & 1);
                    int row = warp * 16 + gID + ((i >= 2) ? 8 : 0);
                    if (col > row) sv = -1e30f;
                }
                s[nt][i] = sv;
                if (i < 2) mx0 = fmaxf(mx0, sv); else mx1 = fmaxf(mx1, sv);
            }
        }
        mx0 = fmaxf(mx0, __shfl_xor_sync(0xffffffffu, mx0, 1));
        mx0 = fmaxf(mx0, __shfl_xor_sync(0xffffffffu, mx0, 2));
        mx1 = fmaxf(mx1, __shfl_xor_sync(0xffffffffu, mx1, 1));
        mx1 = fmaxf(mx1, __shfl_xor_sync(0xffffffffu, mx1, 2));

        float m0n = fmaxf(m0, mx0), m1n = fmaxf(m1, mx1);
        float c0 = exp2f((m0 - m0n) * LOG2E), c1 = exp2f((m1 - m1n) * LOG2E);
        float rs0 = 0.f, rs1 = 0.f;
#pragma unroll
        for (int nt = 0; nt < 8; nt++) {
#pragma unroll
            for (int i = 0; i < 4; i++) {
                float mN = (i < 2) ? m0n : m1n;
                float p = exp2f((s[nt][i] - mN) * LOG2E);
                s[nt][i] = p;
                if (i < 2) rs0 += p; else rs1 += p;
            }
        }
        rs0 += __shfl_xor_sync(0xffffffffu, rs0, 1);
        rs0 += __shfl_xor_sync(0xffffffffu, rs0, 2);
        rs1 += __shfl_xor_sync(0xffffffffu, rs1, 1);
        rs1 += __shfl_xor_sync(0xffffffffu, rs1, 2);
        l0 = l0 * c0 + rs0;
        l1 = l1 * c1 + rs1;
        m0 = m0n; m1 = m1n;
#pragma unroll
        for (int nt = 0; nt < 8; nt++) {
            o[nt][0] *= c0; o[nt][1] *= c0; o[nt][2] *= c1; o[nt][3] *= c1;
        }

        // Write P (tf32) into QP (each warp writes only its own 16 rows)
        {
            int r0 = warp * 16 + gID;
#pragma unroll
            for (int nt = 0; nt < 8; nt++) {
                int cb = nt * 8 + 2 * tig;
                QP[r0 * LD + cb]           = f2tf32(s[nt][0]);
                QP[r0 * LD + cb + 1]       = f2tf32(s[nt][1]);
                QP[(r0 + 8) * LD + cb]     = f2tf32(s[nt][2]);
                QP[(r0 + 8) * LD + cb + 1] = f2tf32(s[nt][3]);
            }
        }
        __syncthreads();  // all warps done reading K before V overwrite

        // Load V tile into KV
        {
            const float* vb = vb0 + (size_t)j * 64 * KVW;
#pragma unroll
            for (int p = 0; p < 8; p++) {
                int r = p * 8 + (tid >> 4), c4 = (tid & 15) << 2;
                float4 v = *reinterpret_cast<const float4*>(vb + (size_t)r * KVW + c4);
                uint32_t* d = &KV[r * LD + c4];
                d[0] = f2tf32(v.x); d[1] = f2tf32(v.y); d[2] = f2tf32(v.z); d[3] = f2tf32(v.w);
            }
        }
        __syncthreads();

        // O += P * V
#pragma unroll
        for (int ks = 0; ks < 8; ks++) {
            uint32_t af[4];
            int r0 = warp * 16;
            af[0] = QP[(r0 + gID) * LD + ks * 8 + tig];
            af[1] = QP[(r0 + gID + 8) * LD + ks * 8 + tig];
            af[2] = QP[(r0 + gID) * LD + ks * 8 + tig + 4];
            af[3] = QP[(r0 + gID + 8) * LD + ks * 8 + tig + 4];
#pragma unroll
            for (int nt = 0; nt < 8; nt++) {
                uint32_t bf[2];
                bf[0] = KV[(ks * 8 + tig) * LD + nt * 8 + gID];
                bf[1] = KV[(ks * 8 + tig + 4) * LD + nt * 8 + gID];
                mma8(o[nt], af, bf, o[nt]);
            }
        }
    }

    // Normalize and write out
    float i0 = 1.f / l0, i1 = 1.f / l1;
    float* ob = go + (size_t)(b * S_ + qi * 64 + warp * 16) * DM + h * DH;
#pragma unroll
    for (int nt = 0; nt < 8; nt++) {
        int cc = nt * 8 + 2 * tig;
        *reinterpret_cast<float2*>(ob + (size_t)gID * DM + cc) =
            make_float2(o[nt][0] * i0, o[nt][1] * i0);
        *reinterpret_cast<float2*>(ob + (size_t)(gID + 8) * DM + cc) =
            make_float2(o[nt][2] * i1, o[nt][3] * i1);
    }
}

// ---------------------------------------------------------------------------
extern "C" void kernel_launch(void* const* d_in, const int* in_sizes, int n_in,
                              void* d_out, int out_size)
{
    const float* residual = (const float*)d_in[0];
    const float* Wq = (const float*)d_in[1];
    const float* Wk = (const float*)d_in[2];
    const float* Wv = (const float*)d_in[3];
    const float* Wo = (const float*)d_in[4];
    float* out = (float*)d_out;

    float *q, *k, *v, *attn;
    cudaGetSymbolAddress((void**)&q, g_q);
    cudaGetSymbolAddress((void**)&k, g_k);
    cudaGetSymbolAddress((void**)&v, g_v);
    cudaGetSymbolAddress((void**)&attn, g_attn);

    const int M = B_ * S_;  // 4096

    // QKV projections: C = residual * W^T  (W is [nh, d_model], K contiguous)
    gemm_tf32<true><<<dim3((NH * DH) / 128, M / 128), 256>>>(residual, Wq, q, M, NH * DH, DM);
    gemm_tf32<true><<<dim3((NKV * DH) / 128, M / 128), 256>>>(residual, Wk, k, M, NKV * DH, DM);
    gemm_tf32<true><<<dim3((NKV * DH) / 128, M / 128), 256>>>(residual, Wv, v, M, NKV * DH, DM);

    // Flash attention: grid (q tiles, heads, batch)
    flash_kernel<<<dim3(S_ / 64, NH, B_), 128>>>(q, k, v, attn);

    // Output projection: out = attn * W_O  (contraction over nh rows, N contiguous)
    gemm_tf32<false><<<dim3(DM / 128, M / 128), 256>>>(attn, Wo, out, M, DM, DM);
}

// round 4
// speedup vs baseline: 1.0067x; 1.0067x over previous
#include <cuda_runtime.h>
#include <cstdint>

#define DEV_INLINE __device__ __forceinline__

constexpr int B_  = 2;
constexpr int S_  = 2048;
constexpr int DM  = 2048;   // d_model
constexpr int NH  = 32;     // heads
constexpr int NKV = 8;      // kv heads
constexpr int DH  = 64;     // head dim
constexpr int KVW = NKV * DH;  // 512
constexpr float LOG2E = 1.4426950408889634f;

// Scratch (device globals — no runtime allocation allowed)
__device__ float g_q[(size_t)B_ * S_ * NH * DH];      // [B*S, 2048]
__device__ float g_k[(size_t)B_ * S_ * NKV * DH];     // [B*S, 512]
__device__ float g_v[(size_t)B_ * S_ * NKV * DH];     // [B*S, 512]
__device__ float g_attn[(size_t)B_ * S_ * NH * DH];   // [B*S, 2048]

DEV_INLINE uint32_t f2tf32(float x) {
    uint32_t u;
    asm("cvt.rna.tf32.f32 %0, %1;" : "=r"(u) : "f"(x));
    return u;
}

DEV_INLINE void mma8(float* d, const uint32_t* a, const uint32_t* b, const float* c) {
    asm volatile(
        "mma.sync.aligned.m16n8k8.row.col.f32.tf32.tf32.f32 "
        "{%0,%1,%2,%3}, {%4,%5,%6,%7}, {%8,%9}, {%10,%11,%12,%13};\n"
        : "=f"(d[0]), "=f"(d[1]), "=f"(d[2]), "=f"(d[3])
        : "r"(a[0]), "r"(a[1]), "r"(a[2]), "r"(a[3]),
          "r"(b[0]), "r"(b[1]),
          "f"(c[0]), "f"(c[1]), "f"(c[2]), "f"(c[3]));
}

DEV_INLINE uint32_t smem_u32(const void* p) {
    return (uint32_t)__cvta_generic_to_shared(p);
}

DEV_INLINE void cp16(uint32_t dst, const void* src) {
    asm volatile("cp.async.cg.shared.global [%0], [%1], 16;\n" :: "r"(dst), "l"(src));
}
DEV_INLINE void cp_commit() { asm volatile("cp.async.commit_group;\n" ::: "memory"); }
template <int N> DEV_INLINE void cp_wait() {
    asm volatile("cp.async.wait_group %0;\n" :: "n"(N) : "memory");
}

// ---------------------------------------------------------------------------
// tf32 GEMM, cp.async 2-stage pipelined, dynamic smem, cvt-on-consume.
//   TRANS_B = true :  C[M,N] = A[M,K] * B[N,K]^T   (A,B row-major, K contiguous)
//   TRANS_B = false:  C[M,N] = A[M,K] * B[K,N]     (B row-major, N contiguous)
// Block tile 128x128x32, 256 threads (8 warps, 2x4), warp tile 64x32.
// ---------------------------------------------------------------------------
template <bool TRANS_B>
__global__ void __launch_bounds__(256)
gemm_tf32(const float* __restrict__ A, const float* __restrict__ Bm,
          float* __restrict__ C, int M, int N, int K)
{
    constexpr int BM = 128, BN = 128, BK = 32;
    constexpr int LDA = BK + 4;                          // 36
    constexpr int LDB = TRANS_B ? (BK + 4) : (BN + 4);   // 36 or 132
    constexpr int ASZ = BM * LDA;
    constexpr int BSZ = TRANS_B ? (BN * LDB) : (BK * LDB);

    extern __shared__ char smem_raw[];
    float* As = reinterpret_cast<float*>(smem_raw);      // [2][ASZ]
    float* Bs = As + 2 * ASZ;                            // [2][BSZ]

    const int tid  = threadIdx.x;
    const int warp = tid >> 5, lane = tid & 31;
    const int gID  = lane >> 2, tig = lane & 3;
    const int wm   = warp >> 2, wn = warp & 3;
    const int bm   = blockIdx.y * BM, bn = blockIdx.x * BN;

    float acc[4][4][4] = {};

    auto loadA = [&](int buf, int k0) {
        float* dst = As + buf * ASZ;
#pragma unroll
        for (int p = 0; p < 4; p++) {
            int r = p * 32 + (tid >> 3), c4 = (tid & 7) << 2;
            cp16(smem_u32(dst + r * LDA + c4), A + (size_t)(bm + r) * K + k0 + c4);
        }
    };
    auto loadB = [&](int buf, int k0) {
        float* dst = Bs + buf * BSZ;
        if constexpr (TRANS_B) {
#pragma unroll
            for (int p = 0; p < 4; p++) {
                int r = p * 32 + (tid >> 3), c4 = (tid & 7) << 2;
                cp16(smem_u32(dst + r * LDB + c4), Bm + (size_t)(bn + r) * K + k0 + c4);
            }
        } else {
#pragma unroll
            for (int p = 0; p < 4; p++) {
                int r = p * 8 + (tid >> 5), c4 = (tid & 31) << 2;
                cp16(smem_u32(dst + r * LDB + c4), Bm + (size_t)(k0 + r) * N + bn + c4);
            }
        }
    };

    const int KT = K / BK;
    loadA(0, 0); loadB(0, 0); cp_commit();

    int buf = 0;
    for (int kt = 0; kt < KT; ++kt) {
        cp_wait<0>();
        __syncthreads();
        if (kt + 1 < KT) {
            loadA(buf ^ 1, (kt + 1) * BK);
            loadB(buf ^ 1, (kt + 1) * BK);
            cp_commit();
        }
        const float* as = As + buf * ASZ;
        const float* bs = Bs + buf * BSZ;

#pragma unroll
        for (int ks = 0; ks < 4; ks++) {
            uint32_t af[4][4], bf[4][2];
#pragma unroll
            for (int mt = 0; mt < 4; mt++) {
                int r = wm * 64 + mt * 16, c = ks * 8;
                af[mt][0] = f2tf32(as[(r + gID) * LDA + c + tig]);
                af[mt][1] = f2tf32(as[(r + gID + 8) * LDA + c + tig]);
                af[mt][2] = f2tf32(as[(r + gID) * LDA + c + tig + 4]);
                af[mt][3] = f2tf32(as[(r + gID + 8) * LDA + c + tig + 4]);
            }
#pragma unroll
            for (int nt = 0; nt < 4; nt++) {
                int n = wn * 32 + nt * 8 + gID;
                int kk = ks * 8 + tig;
                if constexpr (TRANS_B) {
                    bf[nt][0] = f2tf32(bs[n * LDB + kk]);
                    bf[nt][1] = f2tf32(bs[n * LDB + kk + 4]);
                } else {
                    bf[nt][0] = f2tf32(bs[kk * LDB + n]);
                    bf[nt][1] = f2tf32(bs[(kk + 4) * LDB + n]);
                }
            }
#pragma unroll
            for (int mt = 0; mt < 4; mt++)
#pragma unroll
                for (int nt = 0; nt < 4; nt++)
                    mma8(acc[mt][nt], af[mt], bf[nt], acc[mt][nt]);
        }
        buf ^= 1;
    }

    // Epilogue
#pragma unroll
    for (int mt = 0; mt < 4; mt++) {
        int r0 = bm + wm * 64 + mt * 16 + gID;
#pragma unroll
        for (int nt = 0; nt < 4; nt++) {
            int cc = bn + wn * 32 + nt * 8 + 2 * tig;
            *reinterpret_cast<float2*>(C + (size_t)r0 * N + cc) =
                make_float2(acc[mt][nt][0], acc[mt][nt][1]);
            *reinterpret_cast<float2*>(C + (size_t)(r0 + 8) * N + cc) =
                make_float2(acc[mt][nt][2], acc[mt][nt][3]);
        }
    }
}

// ---------------------------------------------------------------------------
// Flash attention (causal, GQA). Block = one (b, head, 64-row q tile).
// 128 threads (4 warps), each warp owns 16 q rows. Q kept in registers as
// A-fragments. Separate K and V smem buffers loaded together (MLP 16),
// only 2 __syncthreads per KV tile; P tile is warp-private (syncwarp only).
// ---------------------------------------------------------------------------
__global__ void __launch_bounds__(128)
flash_kernel(const float* __restrict__ gq, const float* __restrict__ gk,
             const float* __restrict__ gv, float* __restrict__ go)
{
    constexpr int LD  = DH + 4;   // 68
    constexpr int TSZ = 64 * LD;  // 4352 words
    extern __shared__ char smem_raw[];
    uint32_t* QP = reinterpret_cast<uint32_t*>(smem_raw);  // Q tile, reused for P
    uint32_t* Ks = QP + TSZ;
    uint32_t* Vs = Ks + TSZ;

    const int qi = blockIdx.x, h = blockIdx.y, b = blockIdx.z;
    const int kvh = h >> 2;  // rep = NH/NKV = 4
    const int tid = threadIdx.x, warp = tid >> 5, lane = tid & 31;
    const int gID = lane >> 2, tig = lane & 3;

    // Load Q tile (tf32)
    {
        const float* qb = gq + (size_t)(b * S_ + qi * 64) * DM + h * DH;
#pragma unroll
        for (int p = 0; p < 8; p++) {
            int r = p * 8 + (tid >> 4), c4 = (tid & 15) << 2;
            float4 v = *reinterpret_cast<const float4*>(qb + (size_t)r * DM + c4);
            uint32_t* d = &QP[r * LD + c4];
            d[0] = f2tf32(v.x); d[1] = f2tf32(v.y); d[2] = f2tf32(v.z); d[3] = f2tf32(v.w);
        }
    }
    __syncthreads();

    // Pull Q into register A-fragments (16 rows x 64 cols per warp)
    uint32_t qf[8][4];
    {
        int r0 = warp * 16;
#pragma unroll
        for (int ks = 0; ks < 8; ks++) {
            int c = ks * 8;
            qf[ks][0] = QP[(r0 + gID) * LD + c + tig];
            qf[ks][1] = QP[(r0 + gID + 8) * LD + c + tig];
            qf[ks][2] = QP[(r0 + gID) * LD + c + tig + 4];
            qf[ks][3] = QP[(r0 + gID + 8) * LD + c + tig + 4];
        }
    }

    float m0 = -1e30f, m1 = -1e30f, l0 = 0.f, l1 = 0.f;
    float o[8][4];
#pragma unroll
    for (int nt = 0; nt < 8; nt++)
#pragma unroll
        for (int i = 0; i < 4; i++) o[nt][i] = 0.f;

    const float* kb0 = gk + (size_t)(b * S_) * KVW + kvh * DH;
    const float* vb0 = gv + (size_t)(b * S_) * KVW + kvh * DH;

    for (int j = 0; j <= qi; j++) {
        __syncthreads();  // all warps done reading Ks/Vs from previous iter

        // Load K and V tiles together: stage LDGs in regs (MLP 16), then cvt+STS
        {
            const float* kb = kb0 + (size_t)j * 64 * KVW;
            const float* vb = vb0 + (size_t)j * 64 * KVW;
            float4 kr[8], vr[8];
#pragma unroll
            for (int p = 0; p < 8; p++) {
                int r = p * 8 + (tid >> 4), c4 = (tid & 15) << 2;
                kr[p] = *reinterpret_cast<const float4*>(kb + (size_t)r * KVW + c4);
                vr[p] = *reinterpret_cast<const float4*>(vb + (size_t)r * KVW + c4);
            }
#pragma unroll
            for (int p = 0; p < 8; p++) {
                int r = p * 8 + (tid >> 4), c4 = (tid & 15) << 2;
                uint32_t* dk = &Ks[r * LD + c4];
                dk[0] = f2tf32(kr[p].x); dk[1] = f2tf32(kr[p].y);
                dk[2] = f2tf32(kr[p].z); dk[3] = f2tf32(kr[p].w);
                uint32_t* dv = &Vs[r * LD + c4];
                dv[0] = f2tf32(vr[p].x); dv[1] = f2tf32(vr[p].y);
                dv[2] = f2tf32(vr[p].z); dv[3] = f2tf32(vr[p].w);
            }
        }
        __syncthreads();

        // S = Q * K^T (16 rows x 64 key cols per warp)
        float s[8][4];
#pragma unroll
        for (int nt = 0; nt < 8; nt++)
#pragma unroll
            for (int i = 0; i < 4; i++) s[nt][i] = 0.f;
#pragma unroll
        for (int ks = 0; ks < 8; ks++) {
#pragma unroll
            for (int nt = 0; nt < 8; nt++) {
                uint32_t bf[2];
                bf[0] = Ks[(nt * 8 + gID) * LD + ks * 8 + tig];
                bf[1] = Ks[(nt * 8 + gID) * LD + ks * 8 + tig + 4];
                mma8(s[nt], qf[ks], bf, s[nt]);
            }
        }

        // Scale + causal mask + online softmax
        const bool diag = (j == qi);
        float mx0 = -1e30f, mx1 = -1e30f;
#pragma unroll
        for (int nt = 0; nt < 8; nt++) {
#pragma unroll
            for (int i = 0; i < 4; i++) {
                float sv = s[nt][i] * 0.125f;  // 1/sqrt(64)
                if (diag) {
                    int col = nt * 8 + 2 * tig + (i & 1);
                    int row = warp * 16 + gID + ((i >= 2) ? 8 : 0);
                    if (col > row) sv = -1e30f;
                }
                s[nt][i] = sv;
                if (i < 2) mx0 = fmaxf(mx0, sv); else mx1 = fmaxf(mx1, sv);
            }
        }
        mx0 = fmaxf(mx0, __shfl_xor_sync(0xffffffffu, mx0, 1));
        mx0 = fmaxf(mx0, __shfl_xor_sync(0xffffffffu, mx0, 2));
        mx1 = fmaxf(mx1, __shfl_xor_sync(0xffffffffu, mx1, 1));
        mx1 = fmaxf(mx1, __shfl_xor_sync(0xffffffffu, mx1, 2));

        float m0n = fmaxf(m0, mx0), m1n = fmaxf(m1, mx1);
        float c0 = exp2f((m0 - m0n) * LOG2E), c1 = exp2f((m1 - m1n) * LOG2E);
        float rs0 = 0.f, rs1 = 0.f;
#pragma unroll
        for (int nt = 0; nt < 8; nt++) {
#pragma unroll
            for (int i = 0; i < 4; i++) {
                float mN = (i < 2) ? m0n : m1n;
                float p = exp2f((s[nt][i] - mN) * LOG2E);
                s[nt][i] = p;
                if (i < 2) rs0 += p; else rs1 += p;
            }
        }
        rs0 += __shfl_xor_sync(0xffffffffu, rs0, 1);
        rs0 += __shfl_xor_sync(0xffffffffu, rs0, 2);
        rs1 += __shfl_xor_sync(0xffffffffu, rs1, 1);
        rs1 += __shfl_xor_sync(0xffffffffu, rs1, 2);
        l0 = l0 * c0 + rs0;
        l1 = l1 * c1 + rs1;
        m0 = m0n; m1 = m1n;
#pragma unroll
        for (int nt = 0; nt < 8; nt++) {
            o[nt][0] *= c0; o[nt][1] *= c0; o[nt][2] *= c1; o[nt][3] *= c1;
        }

        // Write P (tf32) into QP — warp-private 16 rows, no block sync needed
        {
            int r0 = warp * 16 + gID;
#pragma unroll
            for (int nt = 0; nt < 8; nt++) {
                int cb = nt * 8 + 2 * tig;
                QP[r0 * LD + cb]           = f2tf32(s[nt][0]);
                QP[r0 * LD + cb + 1]       = f2tf32(s[nt][1]);
                QP[(r0 + 8) * LD + cb]     = f2tf32(s[nt][2]);
                QP[(r0 + 8) * LD + cb + 1] = f2tf32(s[nt][3]);
            }
        }
        __syncwarp();  // intra-warp smem RAW on P

        // O += P * V
#pragma unroll
        for (int ks = 0; ks < 8; ks++) {
            uint32_t af[4];
            int r0 = warp * 16;
            af[0] = QP[(r0 + gID) * LD + ks * 8 + tig];
            af[1] = QP[(r0 + gID + 8) * LD + ks * 8 + tig];
            af[2] = QP[(r0 + gID) * LD + ks * 8 + tig + 4];
            af[3] = QP[(r0 + gID + 8) * LD + ks * 8 + tig + 4];
#pragma unroll
            for (int nt = 0; nt < 8; nt++) {
                uint32_t bf[2];
                bf[0] = Vs[(ks * 8 + tig) * LD + nt * 8 + gID];
                bf[1] = Vs[(ks * 8 + tig + 4) * LD + nt * 8 + gID];
                mma8(o[nt], af, bf, o[nt]);
            }
        }
    }

    // Normalize and write out
    float i0 = 1.f / l0, i1 = 1.f / l1;
    float* ob = go + (size_t)(b * S_ + qi * 64 + warp * 16) * DM + h * DH;
#pragma unroll
    for (int nt = 0; nt < 8; nt++) {
        int cc = nt * 8 + 2 * tig;
        *reinterpret_cast<float2*>(ob + (size_t)gID * DM + cc) =
            make_float2(o[nt][0] * i0, o[nt][1] * i0);
        *reinterpret_cast<float2*>(ob + (size_t)(gID + 8) * DM + cc) =
            make_float2(o[nt][2] * i1, o[nt][3] * i1);
    }
}

// ---------------------------------------------------------------------------
extern "C" void kernel_launch(void* const* d_in, const int* in_sizes, int n_in,
                              void* d_out, int out_size)
{
    const float* residual = (const float*)d_in[0];
    const float* Wq = (const float*)d_in[1];
    const float* Wk = (const float*)d_in[2];
    const float* Wv = (const float*)d_in[3];
    const float* Wo = (const float*)d_in[4];
    float* out = (float*)d_out;

    float *q, *k, *v, *attn;
    cudaGetSymbolAddress((void**)&q, g_q);
    cudaGetSymbolAddress((void**)&k, g_k);
    cudaGetSymbolAddress((void**)&v, g_v);
    cudaGetSymbolAddress((void**)&attn, g_attn);

    const int M = B_ * S_;  // 4096

    constexpr int GEMM_SMEM_T = 2 * (128 * 36 + 128 * 36) * 4;  // 73728
    constexpr int GEMM_SMEM_N = 2 * (128 * 36 + 32 * 132) * 4;  // 70656
    constexpr int FLASH_SMEM  = 3 * 64 * 68 * 4;                // 52224

    cudaFuncSetAttribute(gemm_tf32<true>,
                         cudaFuncAttributeMaxDynamicSharedMemorySize, GEMM_SMEM_T);
    cudaFuncSetAttribute(gemm_tf32<false>,
                         cudaFuncAttributeMaxDynamicSharedMemorySize, GEMM_SMEM_N);
    cudaFuncSetAttribute(flash_kernel,
                         cudaFuncAttributeMaxDynamicSharedMemorySize, FLASH_SMEM);

    // QKV projections: C = residual * W^T  (W is [nh, d_model], K contiguous)
    gemm_tf32<true><<<dim3((NH * DH) / 128, M / 128), 256, GEMM_SMEM_T>>>(
        residual, Wq, q, M, NH * DH, DM);
    gemm_tf32<true><<<dim3((NKV * DH) / 128, M / 128), 256, GEMM_SMEM_T>>>(
        residual, Wk, k, M, NKV * DH, DM);
    gemm_tf32<true><<<dim3((NKV * DH) / 128, M / 128), 256, GEMM_SMEM_T>>>(
        residual, Wv, v, M, NKV * DH, DM);

    // Flash attention: grid (q tiles, heads, batch)
    flash_kernel<<<dim3(S_ / 64, NH, B_), 128, FLASH_SMEM>>>(q, k, v, attn);

    // Output projection: out = attn * W_O  (contraction over nh rows, N contiguous)
    gemm_tf32<false><<<dim3(DM / 128, M / 128), 256, GEMM_SMEM_N>>>(
        attn, Wo, out, M, DM, DM);
}

// round 6
// speedup vs baseline: 1.1069x; 1.0996x over previous
#include <cuda_runtime.h>
#include <cstdint>

#define DEV_INLINE __device__ __forceinline__

constexpr int B_  = 2;
constexpr int S_  = 2048;
constexpr int DM  = 2048;   // d_model
constexpr int NH  = 32;     // heads
constexpr int NKV = 8;      // kv heads
constexpr int DH  = 64;     // head dim
constexpr int KVW = NKV * DH;  // 512
constexpr float LOG2E = 1.4426950408889634f;

// Scratch (device globals — no runtime allocation allowed)
__device__ float g_q[(size_t)B_ * S_ * NH * DH];      // [B*S, 2048]  (tf32-rounded)
__device__ float g_k[(size_t)B_ * S_ * NKV * DH];     // [B*S, 512]   (tf32-rounded)
__device__ float g_v[(size_t)B_ * S_ * NKV * DH];     // [B*S, 512]   (tf32-rounded)
__device__ float g_attn[(size_t)B_ * S_ * NH * DH];   // [B*S, 2048]  (tf32-rounded)
// Pre-converted (tf32-rounded) inputs
__device__ float g_resc[(size_t)B_ * S_ * DM];
__device__ float g_wq[(size_t)NH  * DH * DM];
__device__ float g_wk[(size_t)NKV * DH * DM];
__device__ float g_wv[(size_t)NKV * DH * DM];
__device__ float g_wo[(size_t)NH  * DH * DM];

DEV_INLINE uint32_t f2tf32(float x) {
    uint32_t u;
    asm("cvt.rna.tf32.f32 %0, %1;" : "=r"(u) : "f"(x));
    return u;
}
DEV_INLINE float rtf(float x) { return __uint_as_float(f2tf32(x)); }

DEV_INLINE void mma8(float* d, const uint32_t* a, const uint32_t* b, const float* c) {
    asm volatile(
        "mma.sync.aligned.m16n8k8.row.col.f32.tf32.tf32.f32 "
        "{%0,%1,%2,%3}, {%4,%5,%6,%7}, {%8,%9}, {%10,%11,%12,%13};\n"
        : "=f"(d[0]), "=f"(d[1]), "=f"(d[2]), "=f"(d[3])
        : "r"(a[0]), "r"(a[1]), "r"(a[2]), "r"(a[3]),
          "r"(b[0]), "r"(b[1]),
          "f"(c[0]), "f"(c[1]), "f"(c[2]), "f"(c[3]));
}

DEV_INLINE uint32_t smem_u32(const void* p) {
    return (uint32_t)__cvta_generic_to_shared(p);
}
DEV_INLINE void cp16(uint32_t dst, const void* src) {
    asm volatile("cp.async.cg.shared.global [%0], [%1], 16;\n" :: "r"(dst), "l"(src));
}
DEV_INLINE void cp_commit() { asm volatile("cp.async.commit_group;\n" ::: "memory"); }
template <int N> DEV_INLINE void cp_wait() {
    asm volatile("cp.async.wait_group %0;\n" :: "n"(N) : "memory");
}

// ---------------------------------------------------------------------------
// Elementwise tf32 (rna) pre-conversion: out[i] = round_tf32(in[i])
// ---------------------------------------------------------------------------
__global__ void __launch_bounds__(256)
cvt_kernel(const float* __restrict__ in, float* __restrict__ out, int n4)
{
    int i = blockIdx.x * blockDim.x + threadIdx.x;
    if (i >= n4) return;
    float4 v = reinterpret_cast<const float4*>(in)[i];
    v.x = rtf(v.x); v.y = rtf(v.y); v.z = rtf(v.z); v.w = rtf(v.w);
    reinterpret_cast<float4*>(out)[i] = v;
}

// ---------------------------------------------------------------------------
// tf32 GEMM, cp.async 2-stage pipelined. Inputs are PRE-ROUNDED to tf32, so
// the hot loop has zero cvt: fragments are plain LDS of the fp32 bit pattern.
//   TRANS_B = true :  C[M,N] = A[M,K] * B[N,K]^T
//   TRANS_B = false:  C[M,N] = A[M,K] * B[K,N]
//   CVT_OUT = true : epilogue stores tf32-rounded values (for q/k/v scratch)
// Block tile 128x128x32, 256 threads (8 warps, 2x4), warp tile 64x32.
// ---------------------------------------------------------------------------
template <bool TRANS_B, bool CVT_OUT>
__global__ void __launch_bounds__(256)
gemm_tf32(const float* __restrict__ A, const float* __restrict__ Bm,
          float* __restrict__ C, int M, int N, int K)
{
    constexpr int BM = 128, BN = 128, BK = 32;
    constexpr int LDA = BK + 4;                          // 36
    constexpr int LDB = TRANS_B ? (BK + 4) : (BN + 4);   // 36 or 132
    constexpr int ASZ = BM * LDA;
    constexpr int BSZ = TRANS_B ? (BN * LDB) : (BK * LDB);

    extern __shared__ char smem_raw[];
    float* As = reinterpret_cast<float*>(smem_raw);      // [2][ASZ]
    float* Bs = As + 2 * ASZ;                            // [2][BSZ]

    const int tid  = threadIdx.x;
    const int warp = tid >> 5, lane = tid & 31;
    const int gID  = lane >> 2, tig = lane & 3;
    const int wm   = warp >> 2, wn = warp & 3;
    const int bm   = blockIdx.y * BM, bn = blockIdx.x * BN;

    float acc[4][4][4] = {};

    auto loadA = [&](int buf, int k0) {
        float* dst = As + buf * ASZ;
#pragma unroll
        for (int p = 0; p < 4; p++) {
            int r = p * 32 + (tid >> 3), c4 = (tid & 7) << 2;
            cp16(smem_u32(dst + r * LDA + c4), A + (size_t)(bm + r) * K + k0 + c4);
        }
    };
    auto loadB = [&](int buf, int k0) {
        float* dst = Bs + buf * BSZ;
        if constexpr (TRANS_B) {
#pragma unroll
            for (int p = 0; p < 4; p++) {
                int r = p * 32 + (tid >> 3), c4 = (tid & 7) << 2;
                cp16(smem_u32(dst + r * LDB + c4), Bm + (size_t)(bn + r) * K + k0 + c4);
            }
        } else {
#pragma unroll
            for (int p = 0; p < 4; p++) {
                int r = p * 8 + (tid >> 5), c4 = (tid & 31) << 2;
                cp16(smem_u32(dst + r * LDB + c4), Bm + (size_t)(k0 + r) * N + bn + c4);
            }
        }
    };

    const int KT = K / BK;
    loadA(0, 0); loadB(0, 0); cp_commit();

    int buf = 0;
    for (int kt = 0; kt < KT; ++kt) {
        cp_wait<0>();
        __syncthreads();
        if (kt + 1 < KT) {
            loadA(buf ^ 1, (kt + 1) * BK);
            loadB(buf ^ 1, (kt + 1) * BK);
            cp_commit();
        }
        const float* as = As + buf * ASZ;
        const float* bs = Bs + buf * BSZ;

#pragma unroll
        for (int ks = 0; ks < 4; ks++) {
            uint32_t af[4][4], bf[4][2];
#pragma unroll
            for (int mt = 0; mt < 4; mt++) {
                int r = wm * 64 + mt * 16, c = ks * 8;
                af[mt][0] = __float_as_uint(as[(r + gID) * LDA + c + tig]);
                af[mt][1] = __float_as_uint(as[(r + gID + 8) * LDA + c + tig]);
                af[mt][2] = __float_as_uint(as[(r + gID) * LDA + c + tig + 4]);
                af[mt][3] = __float_as_uint(as[(r + gID + 8) * LDA + c + tig + 4]);
            }
#pragma unroll
            for (int nt = 0; nt < 4; nt++) {
                int n = wn * 32 + nt * 8 + gID;
                int kk = ks * 8 + tig;
                if constexpr (TRANS_B) {
                    bf[nt][0] = __float_as_uint(bs[n * LDB + kk]);
                    bf[nt][1] = __float_as_uint(bs[n * LDB + kk + 4]);
                } else {
                    bf[nt][0] = __float_as_uint(bs[kk * LDB + n]);
                    bf[nt][1] = __float_as_uint(bs[(kk + 4) * LDB + n]);
                }
            }
#pragma unroll
            for (int mt = 0; mt < 4; mt++)
#pragma unroll
                for (int nt = 0; nt < 4; nt++)
                    mma8(acc[mt][nt], af[mt], bf[nt], acc[mt][nt]);
        }
        buf ^= 1;
    }

    // Epilogue
#pragma unroll
    for (int mt = 0; mt < 4; mt++) {
        int r0 = bm + wm * 64 + mt * 16 + gID;
#pragma unroll
        for (int nt = 0; nt < 4; nt++) {
            int cc = bn + wn * 32 + nt * 8 + 2 * tig;
            float v0 = acc[mt][nt][0], v1 = acc[mt][nt][1];
            float v2 = acc[mt][nt][2], v3 = acc[mt][nt][3];
            if constexpr (CVT_OUT) {
                v0 = rtf(v0); v1 = rtf(v1); v2 = rtf(v2); v3 = rtf(v3);
            }
            *reinterpret_cast<float2*>(C + (size_t)r0 * N + cc) = make_float2(v0, v1);
            *reinterpret_cast<float2*>(C + (size_t)(r0 + 8) * N + cc) = make_float2(v2, v3);
        }
    }
}

// ---------------------------------------------------------------------------
// Flash attention (causal, GQA). Block = one (b, head, 128-row q tile),
// 256 threads (8 warps), each warp owns 16 q rows. K/V tiles are 64 keys,
// loaded by cp.async (inputs pre-rounded to tf32 -> zero cvt on load).
// P tile is warp-private (syncwarp only). 2 __syncthreads per KV tile.
// ---------------------------------------------------------------------------
__global__ void __launch_bounds__(256, 2)
flash_kernel(const float* __restrict__ gq, const float* __restrict__ gk,
             const float* __restrict__ gv, float* __restrict__ go)
{
    constexpr int LD  = DH + 4;    // 68
    constexpr int QSZ = 128 * LD;  // Q tile then P tile (warp-private rows)
    constexpr int TSZ = 64 * LD;
    extern __shared__ char smem_raw[];
    uint32_t* QP = reinterpret_cast<uint32_t*>(smem_raw);
    uint32_t* Ks = QP + QSZ;
    uint32_t* Vs = Ks + TSZ;

    const int qi = blockIdx.x, h = blockIdx.y, b = blockIdx.z;
    const int kvh = h >> 2;  // rep = NH/NKV = 4
    const int tid = threadIdx.x, warp = tid >> 5, lane = tid & 31;
    const int gID = lane >> 2, tig = lane & 3;

    // Load Q tile (128 x 64, already tf32-rounded) via cp.async
    {
        const float* qb = gq + (size_t)(b * S_ + qi * 128) * DM + h * DH;
#pragma unroll
        for (int p = 0; p < 8; p++) {
            int r = p * 16 + (tid >> 4), c4 = (tid & 15) << 2;
            cp16(smem_u32(QP + r * LD + c4), qb + (size_t)r * DM + c4);
        }
        cp_commit(); cp_wait<0>();
    }
    __syncthreads();

    // Pull Q into register A-fragments (16 rows x 64 cols per warp)
    uint32_t qf[8][4];
    {
        int r0 = warp * 16;
#pragma unroll
        for (int ks = 0; ks < 8; ks++) {
            int c = ks * 8;
            qf[ks][0] = QP[(r0 + gID) * LD + c + tig];
            qf[ks][1] = QP[(r0 + gID + 8) * LD + c + tig];
            qf[ks][2] = QP[(r0 + gID) * LD + c + tig + 4];
            qf[ks][3] = QP[(r0 + gID + 8) * LD + c + tig + 4];
        }
    }

    float m0 = -1e30f, m1 = -1e30f, l0 = 0.f, l1 = 0.f;
    float o[8][4];
#pragma unroll
    for (int nt = 0; nt < 8; nt++)
#pragma unroll
        for (int i = 0; i < 4; i++) o[nt][i] = 0.f;

    const float* kb0 = gk + (size_t)(b * S_) * KVW + kvh * DH;
    const float* vb0 = gv + (size_t)(b * S_) * KVW + kvh * DH;

    const int row0 = warp * 16 + gID;          // local q row of this thread
    const int grow0 = qi * 128 + row0;         // global q row (first half)
    const int jmax = 2 * qi + 1;

    for (int j = 0; j <= jmax; j++) {
        __syncthreads();  // all warps done reading Ks/Vs from previous iter

        // Load K and V tiles (64 x 64 each) via cp.async — no cvt needed
        {
            const float* kb = kb0 + (size_t)j * 64 * KVW;
            const float* vb = vb0 + (size_t)j * 64 * KVW;
#pragma unroll
            for (int p = 0; p < 4; p++) {
                int r = p * 16 + (tid >> 4), c4 = (tid & 15) << 2;
                cp16(smem_u32(Ks + r * LD + c4), kb + (size_t)r * KVW + c4);
                cp16(smem_u32(Vs + r * LD + c4), vb + (size_t)r * KVW + c4);
            }
            cp_commit(); cp_wait<0>();
        }
        __syncthreads();

        // S = Q * K^T (16 rows x 64 key cols per warp)
        float s[8][4];
#pragma unroll
        for (int nt = 0; nt < 8; nt++)
#pragma unroll
            for (int i = 0; i < 4; i++) s[nt][i] = 0.f;
#pragma unroll
        for (int ks = 0; ks < 8; ks++) {
#pragma unroll
            for (int nt = 0; nt < 8; nt++) {
                uint32_t bf[2];
                bf[0] = Ks[(nt * 8 + gID) * LD + ks * 8 + tig];
                bf[1] = Ks[(nt * 8 + gID) * LD + ks * 8 + tig + 4];
                mma8(s[nt], qf[ks], bf, s[nt]);
            }
        }

        // Scale + causal mask + online softmax
        const bool diag = (j >= 2 * qi);
        float mx0 = -1e30f, mx1 = -1e30f;
#pragma unroll
        for (int nt = 0; nt < 8; nt++) {
#pragma unroll
            for (int i = 0; i < 4; i++) {
                float sv = s[nt][i] * 0.125f;  // 1/sqrt(64)
                if (diag) {
                    int col = j * 64 + nt * 8 + 2 * tig + (i & 1);
                    int row = grow0 + ((i >= 2) ? 8 : 0);
                    if (col > row) sv = -1e30f;
                }
                s[nt][i] = sv;
                if (i < 2) mx0 = fmaxf(mx0, sv); else mx1 = fmaxf(mx1, sv);
            }
        }
        mx0 = fmaxf(mx0, __shfl_xor_sync(0xffffffffu, mx0, 1));
        mx0 = fmaxf(mx0, __shfl_xor_sync(0xffffffffu, mx0, 2));
        mx1 = fmaxf(mx1, __shfl_xor_sync(0xffffffffu, mx1, 1));
        mx1 = fmaxf(mx1, __shfl_xor_sync(0xffffffffu, mx1, 2));

        float m0n = fmaxf(m0, mx0), m1n = fmaxf(m1, mx1);
        float c0 = exp2f((m0 - m0n) * LOG2E), c1 = exp2f((m1 - m1n) * LOG2E);
        float rs0 = 0.f, rs1 = 0.f;
#pragma unroll
        for (int nt = 0; nt < 8; nt++) {
#pragma unroll
            for (int i = 0; i < 4; i++) {
                float mN = (i < 2) ? m0n : m1n;
                float p = exp2f((s[nt][i] - mN) * LOG2E);
                s[nt][i] = p;
                if (i < 2) rs0 += p; else rs1 += p;
            }
        }
        rs0 += __shfl_xor_sync(0xffffffffu, rs0, 1);
        rs0 += __shfl_xor_sync(0xffffffffu, rs0, 2);
        rs1 += __shfl_xor_sync(0xffffffffu, rs1, 1);
        rs1 += __shfl_xor_sync(0xffffffffu, rs1, 2);
        l0 = l0 * c0 + rs0;
        l1 = l1 * c1 + rs1;
        m0 = m0n; m1 = m1n;
#pragma unroll
        for (int nt = 0; nt < 8; nt++) {
            o[nt][0] *= c0; o[nt][1] *= c0; o[nt][2] *= c1; o[nt][3] *= c1;
        }

        // Write P (tf32) into QP — warp-private 16 rows, no block sync needed
        {
#pragma unroll
            for (int nt = 0; nt < 8; nt++) {
                int cb = nt * 8 + 2 * tig;
                QP[row0 * LD + cb]           = f2tf32(s[nt][0]);
                QP[row0 * LD + cb + 1]       = f2tf32(s[nt][1]);
                QP[(row0 + 8) * LD + cb]     = f2tf32(s[nt][2]);
                QP[(row0 + 8) * LD + cb + 1] = f2tf32(s[nt][3]);
            }
        }
        __syncwarp();  // intra-warp smem RAW on P

        // O += P * V
#pragma unroll
        for (int ks = 0; ks < 8; ks++) {
            uint32_t af[4];
            int r0 = warp * 16;
            af[0] = QP[(r0 + gID) * LD + ks * 8 + tig];
            af[1] = QP[(r0 + gID + 8) * LD + ks * 8 + tig];
            af[2] = QP[(r0 + gID) * LD + ks * 8 + tig + 4];
            af[3] = QP[(r0 + gID + 8) * LD + ks * 8 + tig + 4];
#pragma unroll
            for (int nt = 0; nt < 8; nt++) {
                uint32_t bf[2];
                bf[0] = Vs[(ks * 8 + tig) * LD + nt * 8 + gID];
                bf[1] = Vs[(ks * 8 + tig + 4) * LD + nt * 8 + gID];
                mma8(o[nt], af, bf, o[nt]);
            }
        }
    }

    // Normalize and write out (tf32-rounded: attn feeds the O-proj GEMM)
    float i0 = 1.f / l0, i1 = 1.f / l1;
    float* ob = go + (size_t)(b * S_ + qi * 128 + warp * 16) * DM + h * DH;
#pragma unroll
    for (int nt = 0; nt < 8; nt++) {
        int cc = nt * 8 + 2 * tig;
        *reinterpret_cast<float2*>(ob + (size_t)gID * DM + cc) =
            make_float2(rtf(o[nt][0] * i0), rtf(o[nt][1] * i0));
        *reinterpret_cast<float2*>(ob + (size_t)(gID + 8) * DM + cc) =
            make_float2(rtf(o[nt][2] * i1), rtf(o[nt][3] * i1));
    }
}

// ---------------------------------------------------------------------------
extern "C" void kernel_launch(void* const* d_in, const int* in_sizes, int n_in,
                              void* d_out, int out_size)
{
    const float* residual = (const float*)d_in[0];
    const float* Wq = (const float*)d_in[1];
    const float* Wk = (const float*)d_in[2];
    const float* Wv = (const float*)d_in[3];
    const float* Wo = (const float*)d_in[4];
    float* out = (float*)d_out;

    float *q, *k, *v, *attn, *resc, *wq, *wk, *wv, *wo;
    cudaGetSymbolAddress((void**)&q, g_q);
    cudaGetSymbolAddress((void**)&k, g_k);
    cudaGetSymbolAddress((void**)&v, g_v);
    cudaGetSymbolAddress((void**)&attn, g_attn);
    cudaGetSymbolAddress((void**)&resc, g_resc);
    cudaGetSymbolAddress((void**)&wq, g_wq);
    cudaGetSymbolAddress((void**)&wk, g_wk);
    cudaGetSymbolAddress((void**)&wv, g_wv);
    cudaGetSymbolAddress((void**)&wo, g_wo);

    const int M = B_ * S_;  // 4096

    constexpr int GEMM_SMEM_T = 2 * (128 * 36 + 128 * 36) * 4;  // 73728
    constexpr int GEMM_SMEM_N = 2 * (128 * 36 + 32 * 132) * 4;  // 70656
    constexpr int FLASH_SMEM  = (128 + 64 + 64) * 68 * 4;       // 69632

    cudaFuncSetAttribute(gemm_tf32<true, true>,
                         cudaFuncAttributeMaxDynamicSharedMemorySize, GEMM_SMEM_T);
    cudaFuncSetAttribute(gemm_tf32<false, false>,
                         cudaFuncAttributeMaxDynamicSharedMemorySize, GEMM_SMEM_N);
    cudaFuncSetAttribute(flash_kernel,
                         cudaFuncAttributeMaxDynamicSharedMemorySize, FLASH_SMEM);

    // Pre-convert inputs to tf32 (rna) once
    auto cvt = [](const float* in, float* o2, size_t n) {
        int n4 = (int)(n / 4);
        cvt_kernel<<<(n4 + 255) / 256, 256>>>(in, o2, n4);
    };
    cvt(residual, resc, (size_t)M * DM);
    cvt(Wq, wq, (size_t)NH * DH * DM);
    cvt(Wk, wk, (size_t)NKV * DH * DM);
    cvt(Wv, wv, (size_t)NKV * DH * DM);
    cvt(Wo, wo, (size_t)NH * DH * DM);

    // QKV projections: C = resc * W^T   (epilogue stores tf32-rounded)
    gemm_tf32<true, true><<<dim3((NH * DH) / 128, M / 128), 256, GEMM_SMEM_T>>>(
        resc, wq, q, M, NH * DH, DM);
    gemm_tf32<true, true><<<dim3((NKV * DH) / 128, M / 128), 256, GEMM_SMEM_T>>>(
        resc, wk, k, M, NKV * DH, DM);
    gemm_tf32<true, true><<<dim3((NKV * DH) / 128, M / 128), 256, GEMM_SMEM_T>>>(
        resc, wv, v, M, NKV * DH, DM);

    // Flash attention: grid (128-row q tiles, heads, batch)
    flash_kernel<<<dim3(S_ / 128, NH, B_), 256, FLASH_SMEM>>>(q, k, v, attn);

    // Output projection: out = attn * W_O  (exact fp32 store)
    gemm_tf32<false, false><<<dim3(DM / 128, M / 128), 256, GEMM_SMEM_N>>>(
        attn, wo, out, M, DM, DM);
}